// round 2
// baseline (speedup 1.0000x reference)
#include <cuda_runtime.h>

#define BB 256     // batch
#define TT 256     // time steps
#define DD 64      // input dim
#define HH 512     // hidden
#define OO 10      // output classes

#define NBLK 128   // persistent grid for recurrence (must all be co-resident)

// ---------------- scratch (static device globals; no allocation allowed) ----
__device__ float g_xp0[TT * BB * HH];     // 134 MB  [t][b][h]
__device__ float g_seq0[TT * BB * HH];    // 134 MB  [t][b][h]
__device__ float g_xp1[TT * BB * HH];     // 134 MB  [t][b][h]
__device__ float g_part[2][2][BB * HH];   // ping-pong x split x [b][j]
__device__ float g_hlast[BB * HH];

__device__ unsigned g_cnt = 0;
__device__ unsigned g_gen = 0;

// ---------------- software grid barrier (sense via generation counter) ------
__device__ __forceinline__ void grid_bar(unsigned nb) {
    __syncthreads();
    if (threadIdx.x == 0) {
        __threadfence();
        unsigned snap = atomicAdd(&g_gen, 0u);
        unsigned old = atomicAdd(&g_cnt, 1u);
        if (old == nb - 1u) {
            g_cnt = 0u;
            __threadfence();
            atomicExch(&g_gen, snap + 1u);
        } else {
            while (atomicAdd(&g_gen, 0u) == snap) {}
        }
    }
    __syncthreads();
}

// ---------------- generic  C[m][n] = sum_k A[m][k]*W[n][k] + b1[n] + b2[n] --
// A: [M][K] row-major (optionally rows permuted as x[b][t][d] with m = t*B+b)
// W: [N][K] row-major. Tile 64x64, BK=16, 256 threads, 4x4 micro-tile.
__global__ __launch_bounds__(256) void gemm_nt_bias(
    const float* __restrict__ A, const float* __restrict__ Wm,
    const float* __restrict__ b1, const float* __restrict__ b2,
    float* __restrict__ Cm, int M, int N, int K, int permute)
{
    __shared__ float sA[64 * 16];   // [m][k]
    __shared__ float sW[16 * 64];   // [k][n]

    int m0 = blockIdx.x * 64;
    int n0 = blockIdx.y * 64;
    int tid = threadIdx.x;
    int tn = tid & 15;        // 0..15  (n)
    int tm = tid >> 4;        // 0..15  (m)

    int ar  = tid >> 2;       // 0..63 staging row
    int akq = tid & 3;        // 0..3  staging k-quad

    const float* Arow;
    {
        int gm = m0 + ar;
        if (permute) {
            int b_ = gm & (BB - 1);
            int t_ = gm >> 8;                   // BB == 256
            Arow = A + ((size_t)b_ * TT + t_) * K;
        } else {
            Arow = A + (size_t)gm * K;
        }
    }
    const float* Wrow = Wm + (size_t)(n0 + ar) * K;

    float acc[4][4];
#pragma unroll
    for (int i = 0; i < 4; ++i)
#pragma unroll
        for (int j = 0; j < 4; ++j) acc[i][j] = 0.f;

    for (int kt = 0; kt < K; kt += 16) {
        float4 a4 = *(const float4*)(Arow + kt + akq * 4);
        float4 w4 = *(const float4*)(Wrow + kt + akq * 4);
        __syncthreads();
        *(float4*)&sA[ar * 16 + akq * 4] = a4;
        sW[(akq * 4 + 0) * 64 + ar] = w4.x;
        sW[(akq * 4 + 1) * 64 + ar] = w4.y;
        sW[(akq * 4 + 2) * 64 + ar] = w4.z;
        sW[(akq * 4 + 3) * 64 + ar] = w4.w;
        __syncthreads();

#pragma unroll
        for (int kq = 0; kq < 4; ++kq) {
            float4 av[4], wv[4];
#pragma unroll
            for (int i = 0; i < 4; ++i)
                av[i] = *(const float4*)&sA[(tm * 4 + i) * 16 + kq * 4];
#pragma unroll
            for (int i = 0; i < 4; ++i)
                wv[i] = *(const float4*)&sW[(kq * 4 + i) * 64 + tn * 4];
#pragma unroll
            for (int i = 0; i < 4; ++i) {
                float4 wk = wv[i];
#pragma unroll
                for (int bb2 = 0; bb2 < 4; ++bb2) {
                    float a = (i == 0) ? av[bb2].x : (i == 1) ? av[bb2].y
                             : (i == 2) ? av[bb2].z : av[bb2].w;
                    acc[bb2][0] += a * wk.x;
                    acc[bb2][1] += a * wk.y;
                    acc[bb2][2] += a * wk.z;
                    acc[bb2][3] += a * wk.w;
                }
            }
        }
    }

    float bias[4];
#pragma unroll
    for (int j = 0; j < 4; ++j) {
        int n = n0 + tn * 4 + j;
        bias[j] = b1[n] + (b2 ? b2[n] : 0.f);
    }
#pragma unroll
    for (int i = 0; i < 4; ++i) {
        float4 o;
        o.x = acc[i][0] + bias[0];
        o.y = acc[i][1] + bias[1];
        o.z = acc[i][2] + bias[2];
        o.w = acc[i][3] + bias[3];
        *(float4*)(Cm + (size_t)(m0 + tm * 4 + i) * N + n0 + tn * 4) = o;
    }
}

// ---------------- persistent recurrence kernel ------------------------------
// h_t = relu(xp[t] + h_{t-1} @ Whh^T), split-K=2, combine-on-load next step.
// CTA (bt, jt, s): 32 b-rows x 64 j-cols, k-half s. 128 threads, 4x4 micro.
// Whh slice (64j x 256k) persists in SMEM for all steps.
__global__ __launch_bounds__(128, 1) void rec_kernel(
    const float* __restrict__ xp,      // [T][B][H]
    const float* __restrict__ Whh,     // [H][H]
    float* __restrict__ seq_out,       // [T][B][H] or nullptr
    float* __restrict__ h_last)        // [B][H]    or nullptr
{
    extern __shared__ float smem[];
    float* sW = smem;                  // [256 k][64 j]
    float* sH = smem + 256 * 64;       // [32 b][64 k-chunk]

    const unsigned nb = gridDim.x;
    int cid = blockIdx.x;
    int s  = cid & 1;
    int jt = (cid >> 1) & 7;
    int bt = cid >> 4;
    int b0 = bt * 32, j0 = jt * 64, k0 = s * 256;

    int tid = threadIdx.x;
    int tj = tid & 15;                 // 0..15 (j quads)
    int tb = tid >> 4;                 // 0..7  (b quads)

    // Load Whh slice transposed into sW[k][j] (one time).
    for (int i = tid; i < 64 * 64; i += 128) {
        int kq = i & 63;               // k-quad 0..63  (consecutive -> coalesced)
        int j  = i >> 6;               // 0..63
        float4 w4 = *(const float4*)(Whh + (size_t)(j0 + j) * HH + k0 + kq * 4);
        sW[(kq * 4 + 0) * 64 + j] = w4.x;
        sW[(kq * 4 + 1) * 64 + j] = w4.y;
        sW[(kq * 4 + 2) * 64 + j] = w4.z;
        sW[(kq * 4 + 3) * 64 + j] = w4.w;
    }

    // Zero ping buffer 0 (represents pre-activation partials of h_0 minus xp).
    {
        float4 z = make_float4(0.f, 0.f, 0.f, 0.f);
        float4* pb = (float4*)&g_part[0][0][0];
        int total4 = 2 * BB * HH / 4;
        for (int i = cid * 128 + tid; i < total4; i += (int)nb * 128) pb[i] = z;
    }
    grid_bar(nb);

    const int wr_seq = (seq_out != nullptr) && (jt == 0);

    for (int t = 1; t < TT; ++t) {
        const float* xprev = xp + (size_t)(t - 1) * BB * HH;
        const float* p0 = &g_part[(t - 1) & 1][0][0];
        const float* p1 = &g_part[(t - 1) & 1][1][0];
        float* pw = &g_part[t & 1][s][0];

        float acc[4][4];
#pragma unroll
        for (int i = 0; i < 4; ++i)
#pragma unroll
            for (int j = 0; j < 4; ++j) acc[i][j] = 0.f;

        // Prefetch chunk 0 stage data into registers.
        float4 rx[4], rp0[4], rp1[4];
#pragma unroll
        for (int it = 0; it < 4; ++it) {
            int q = tid + it * 128;
            int b = q >> 4, kq = q & 15;
            size_t off = (size_t)(b0 + b) * HH + k0 + kq * 4;
            rx[it]  = *(const float4*)(xprev + off);
            rp0[it] = *(const float4*)(p0 + off);
            rp1[it] = *(const float4*)(p1 + off);
        }

        for (int c = 0; c < 4; ++c) {
            // Combine + store stage (chunk c) to SMEM; optionally emit seq0.
#pragma unroll
            for (int it = 0; it < 4; ++it) {
                int q = tid + it * 128;
                int b = q >> 4, kq = q & 15;
                float4 v;
                v.x = fmaxf(rx[it].x + rp0[it].x + rp1[it].x, 0.f);
                v.y = fmaxf(rx[it].y + rp0[it].y + rp1[it].y, 0.f);
                v.z = fmaxf(rx[it].z + rp0[it].z + rp1[it].z, 0.f);
                v.w = fmaxf(rx[it].w + rp0[it].w + rp1[it].w, 0.f);
                *(float4*)&sH[b * 64 + kq * 4] = v;
                if (wr_seq) {
                    size_t off = (size_t)(t - 1) * BB * HH +
                                 (size_t)(b0 + b) * HH + k0 + c * 64 + kq * 4;
                    *(float4*)(seq_out + off) = v;
                }
            }
            __syncthreads();

            // Prefetch next chunk while computing this one.
            if (c < 3) {
#pragma unroll
                for (int it = 0; it < 4; ++it) {
                    int q = tid + it * 128;
                    int b = q >> 4, kq = q & 15;
                    size_t off = (size_t)(b0 + b) * HH + k0 + (c + 1) * 64 + kq * 4;
                    rx[it]  = *(const float4*)(xprev + off);
                    rp0[it] = *(const float4*)(p0 + off);
                    rp1[it] = *(const float4*)(p1 + off);
                }
            }

            // Compute: 64 k per chunk, 4x4 micro.
#pragma unroll
            for (int kq2 = 0; kq2 < 16; ++kq2) {
                float4 av[4], wv[4];
#pragma unroll
                for (int i = 0; i < 4; ++i)
                    av[i] = *(const float4*)&sH[(tb * 4 + i) * 64 + kq2 * 4];
#pragma unroll
                for (int i = 0; i < 4; ++i)
                    wv[i] = *(const float4*)&sW[(c * 64 + kq2 * 4 + i) * 64 + tj * 4];
#pragma unroll
                for (int i = 0; i < 4; ++i) {
                    float4 wk = wv[i];
#pragma unroll
                    for (int bb2 = 0; bb2 < 4; ++bb2) {
                        float a = (i == 0) ? av[bb2].x : (i == 1) ? av[bb2].y
                                 : (i == 2) ? av[bb2].z : av[bb2].w;
                        acc[bb2][0] += a * wk.x;
                        acc[bb2][1] += a * wk.y;
                        acc[bb2][2] += a * wk.z;
                        acc[bb2][3] += a * wk.w;
                    }
                }
            }
            __syncthreads();
        }

        // Write split partials for h_t.
#pragma unroll
        for (int i = 0; i < 4; ++i) {
            float4 o;
            o.x = acc[i][0]; o.y = acc[i][1]; o.z = acc[i][2]; o.w = acc[i][3];
            *(float4*)(pw + (size_t)(b0 + tb * 4 + i) * HH + j0 + tj * 4) = o;
        }
        grid_bar(nb);
    }

    // Final combine for h_{T-1}: designated CTAs (jt==0) cover (b, k-half).
    if (jt == 0) {
        const float* xl = xp + (size_t)(TT - 1) * BB * HH;
        const float* p0 = &g_part[(TT - 1) & 1][0][0];
        const float* p1 = &g_part[(TT - 1) & 1][1][0];
        for (int i = tid; i < 32 * 64; i += 128) {   // 32 b-rows x 64 f4 quads
            int b = i >> 6;
            int kq = i & 63;
            size_t off = (size_t)(b0 + b) * HH + k0 + kq * 4;
            float4 x4 = *(const float4*)(xl + off);
            float4 a4 = *(const float4*)(p0 + off);
            float4 c4 = *(const float4*)(p1 + off);
            float4 v;
            v.x = fmaxf(x4.x + a4.x + c4.x, 0.f);
            v.y = fmaxf(x4.y + a4.y + c4.y, 0.f);
            v.z = fmaxf(x4.z + a4.z + c4.z, 0.f);
            v.w = fmaxf(x4.w + a4.w + c4.w, 0.f);
            if (seq_out)
                *(float4*)(seq_out + (size_t)(TT - 1) * BB * HH + off) = v;
            if (h_last)
                *(float4*)(h_last + off) = v;
        }
    }
}

// ---------------- head: relu(h @ fc1^T + b1) @ fc2^T + b2 -------------------
__global__ __launch_bounds__(256) void head_kernel(
    const float* __restrict__ hl, const float* __restrict__ w1,
    const float* __restrict__ b1f, const float* __restrict__ w2,
    const float* __restrict__ b2f, float* __restrict__ out)
{
    __shared__ float sh[8];
    int b = blockIdx.x;
    int tid = threadIdx.x;
    int w = tid >> 5;       // warp = fc1 unit 0..7
    int lane = tid & 31;

    const float* hb = hl + (size_t)b * HH;
    const float* wr = w1 + (size_t)w * HH;
    float ssum = 0.f;
    for (int k = lane; k < HH; k += 32) ssum += hb[k] * wr[k];
#pragma unroll
    for (int o = 16; o; o >>= 1) ssum += __shfl_xor_sync(0xffffffffu, ssum, o);
    if (lane == 0) sh[w] = fmaxf(ssum + b1f[w], 0.f);
    __syncthreads();
    if (tid < OO) {
        float r = b2f[tid];
#pragma unroll
        for (int j = 0; j < 8; ++j) r += sh[j] * w2[tid * 8 + j];
        out[(size_t)b * OO + tid] = r;
    }
}

// ---------------- launch ----------------------------------------------------
extern "C" void kernel_launch(void* const* d_in, const int* in_sizes, int n_in,
                              void* d_out, int out_size)
{
    const float* x     = (const float*)d_in[0];
    const float* w_ih0 = (const float*)d_in[1];
    const float* w_hh0 = (const float*)d_in[2];
    const float* b_ih0 = (const float*)d_in[3];
    const float* b_hh0 = (const float*)d_in[4];
    const float* w_ih1 = (const float*)d_in[5];
    const float* w_hh1 = (const float*)d_in[6];
    const float* b_ih1 = (const float*)d_in[7];
    const float* b_hh1 = (const float*)d_in[8];
    const float* fc1_w = (const float*)d_in[9];
    const float* fc1_b = (const float*)d_in[10];
    const float* fc2_w = (const float*)d_in[11];
    const float* fc2_b = (const float*)d_in[12];
    float* out = (float*)d_out;

    void* p;
    cudaGetSymbolAddress(&p, g_xp0);   float* xp0   = (float*)p;
    cudaGetSymbolAddress(&p, g_seq0);  float* seq0  = (float*)p;
    cudaGetSymbolAddress(&p, g_xp1);   float* xp1   = (float*)p;
    cudaGetSymbolAddress(&p, g_hlast); float* hlast = (float*)p;

    size_t rec_smem = (size_t)(256 * 64 + 32 * 64) * sizeof(float);  // 73728 B
    cudaFuncSetAttribute(rec_kernel,
                         cudaFuncAttributeMaxDynamicSharedMemorySize,
                         (int)rec_smem);

    dim3 gg(TT * BB / 64, HH / 64);   // 1024 x 8

    // layer-0 input projection: xp0[t][b][j], rows permuted from x[b][t][d]
    gemm_nt_bias<<<gg, 256>>>(x, w_ih0, b_ih0, b_hh0, xp0,
                              TT * BB, HH, DD, 1);
    // layer-0 recurrence (writes seq0)
    rec_kernel<<<NBLK, 128, rec_smem>>>(xp0, w_hh0, seq0, nullptr);
    // layer-1 input projection: xp1 = seq0 @ w_ih1^T + biases
    gemm_nt_bias<<<gg, 256>>>(seq0, w_ih1, b_ih1, b_hh1, xp1,
                              TT * BB, HH, HH, 0);
    // layer-1 recurrence (only final hidden state needed)
    rec_kernel<<<NBLK, 128, rec_smem>>>(xp1, w_hh1, nullptr, hlast);
    // head
    head_kernel<<<BB, 256>>>(hlast, fc1_w, fc1_b, fc2_w, fc2_b, out);
}